// round 1
// baseline (speedup 1.0000x reference)
#include <cuda_runtime.h>
#include <math.h>

#define NB 256
#define NT 512
#define NM 16
#define NC 16
#define NH 768
#define G3 (3*NH)

// ---------------- scratch (device globals; no allocation) ----------------
__device__ float g_Z[NB*NT*NM];      // encoder output
__device__ float g_hill[NB*NT*NM];   // hill saturation
__device__ float g_u[NB*NT*NM];      // hill + Z (media part of gru input)
__device__ float g_ads[NB*NT*NM];    // adstock
__device__ float g_cmax[NB*NM];
__device__ float g_ctrl[NB*NT];      // 0.3 * sum relu(Xc@ctrl_w.T + b)
__device__ float g_constant[1];      // reg_term*0.3... actually reg*0.3 + bias
__device__ float g_h[2][NB*NH];      // ping-pong GRU state

// ---------------- encoder: per-sample tiny MLPs ----------------
__global__ void encoder_k(const float* __restrict__ Xm,
                          const float* __restrict__ ew1, const float* __restrict__ eb1,
                          const float* __restrict__ ew2, const float* __restrict__ eb2,
                          const float* __restrict__ nw,  const float* __restrict__ nb,
                          const float* __restrict__ Amat) {
    __shared__ float s_ew1[NM*2*NM], s_ew2[NM*NM], s_nw[NM*2*NM];
    __shared__ float s_eb1[NM], s_eb2[NM], s_nb[NM], s_A[NM*NM];
    int tid = threadIdx.x;
    for (int i = tid; i < NM*2*NM; i += 256) s_ew1[i] = ew1[i];
    for (int i = tid; i < NM*NM;   i += 256) s_ew2[i] = ew2[i];
    for (int i = tid; i < NM*2*NM; i += 256) s_nw[i]  = nw[i];
    for (int i = tid; i < NM*NM;   i += 256) s_A[i]   = Amat[i];
    if (tid < NM) { s_eb1[tid] = eb1[tid]; s_eb2[tid] = eb2[tid]; s_nb[tid] = nb[tid]; }
    __syncthreads();

    int s = blockIdx.x * 256 + tid;   // sample index b*T+t
    float xm[NM];
    const float* xp = Xm + (size_t)s * NM;
    #pragma unroll
    for (int i = 0; i < NM; i++) xm[i] = xp[i];

    // send = Xm @ A.T  -> send[i] = sum_j xm[j]*A[i][j]
    // recv = Xm @ A    -> recv[i] = sum_j xm[j]*A[j][i]
    float send[NM], recv[NM];
    #pragma unroll
    for (int i = 0; i < NM; i++) { send[i] = 0.f; recv[i] = 0.f; }
    #pragma unroll
    for (int j = 0; j < NM; j++) {
        float x = xm[j];
        #pragma unroll
        for (int i = 0; i < NM; i++) {
            send[i] = fmaf(x, s_A[i*NM+j], send[i]);
            recv[i] = fmaf(x, s_A[j*NM+i], recv[i]);
        }
    }
    float he1[NM];
    #pragma unroll
    for (int i = 0; i < NM; i++) {
        float a = s_eb1[i];
        #pragma unroll
        for (int f = 0; f < NM; f++) a = fmaf(send[f], s_ew1[i*2*NM+f], a);
        #pragma unroll
        for (int f = 0; f < NM; f++) a = fmaf(recv[f], s_ew1[i*2*NM+NM+f], a);
        he1[i] = fmaxf(a, 0.f);
    }
    float he2[NM];
    #pragma unroll
    for (int i = 0; i < NM; i++) {
        float a = s_eb2[i];
        #pragma unroll
        for (int f = 0; f < NM; f++) a = fmaf(he1[f], s_ew2[i*NM+f], a);
        he2[i] = fmaxf(a, 0.f);
    }
    float* zp = g_Z + (size_t)s * NM;
    #pragma unroll
    for (int i = 0; i < NM; i++) {
        float a = s_nb[i];
        #pragma unroll
        for (int f = 0; f < NM; f++) a = fmaf(xm[f],  s_nw[i*2*NM+f],    a);
        #pragma unroll
        for (int f = 0; f < NM; f++) a = fmaf(he2[f], s_nw[i*2*NM+NM+f], a);
        zp[i] = fmaxf(a, 0.f);
    }
}

// ---------------- ctrl term: 0.3 * sum_h relu(Xc . ctrl_w[h] + cb[h]) ----------------
__global__ void ctrl_k(const float* __restrict__ Xc,
                       const float* __restrict__ cw, const float* __restrict__ cb) {
    __shared__ float s_w[NH*NC];   // 48KB exactly
    int tid = threadIdx.x;
    for (int i = tid; i < NH*NC; i += 256) s_w[i] = cw[i];
    __syncthreads();

    int s = blockIdx.x * 256 + tid;
    const float4* xp = (const float4*)(Xc + (size_t)s * NC);
    float4 x0 = xp[0], x1 = xp[1], x2 = xp[2], x3 = xp[3];
    float acc = 0.f;
    #pragma unroll 4
    for (int h = 0; h < NH; h++) {
        const float4* w = (const float4*)(s_w + h*NC);
        float4 w0 = w[0], w1 = w[1], w2 = w[2], w3 = w[3];
        float d = __ldg(cb + h);
        d = fmaf(x0.x,w0.x, fmaf(x0.y,w0.y, fmaf(x0.z,w0.z, fmaf(x0.w,w0.w, d))));
        d = fmaf(x1.x,w1.x, fmaf(x1.y,w1.y, fmaf(x1.z,w1.z, fmaf(x1.w,w1.w, d))));
        d = fmaf(x2.x,w2.x, fmaf(x2.y,w2.y, fmaf(x2.z,w2.z, fmaf(x2.w,w2.w, d))));
        d = fmaf(x3.x,w3.x, fmaf(x3.y,w3.y, fmaf(x3.z,w3.z, fmaf(x3.w,w3.w, d))));
        acc += fmaxf(d, 0.f);
    }
    g_ctrl[s] = 0.3f * acc;
}

// ---------------- adstock recurrence per (b,m) chain ----------------
__global__ void adstock_k(const float* __restrict__ Xm, const float* __restrict__ alpha) {
    int tid = blockIdx.x * blockDim.x + threadIdx.x;   // 4096 = NB*NM
    int b = tid >> 4, m = tid & 15;
    float a = fminf(fmaxf(alpha[m], 0.f), 1.f);
    const float* xp = Xm + ((size_t)b * NT) * NM + m;
    float* ap = g_ads + ((size_t)b * NT) * NM + m;
    float prev = 0.f, cm = -1e30f;
    for (int t = 0; t < NT; t++) {
        float x = xp[(size_t)t * NM];
        float cur = (t == 0) ? x : fmaf(a, prev, x);
        ap[(size_t)t * NM] = cur;
        prev = cur;
        cm = fmaxf(cm, cur);
    }
    g_cmax[tid] = fmaxf(cm, 1e-6f);
}

// ---------------- hill saturation + gru media input ----------------
__global__ void hill_k(const float* __restrict__ hill_a, const float* __restrict__ hill_g) {
    size_t idx = (size_t)blockIdx.x * blockDim.x + threadIdx.x;   // NB*NT*NM
    int m = (int)(idx & 15);
    size_t b = idx >> 13;                // idx / (NT*NM)
    float ha = fminf(fmaxf(hill_a[m], 0.1f), 3.0f);
    float hg = fminf(fmaxf(hill_g[m], 0.1f), 2.0f);
    float ads = g_ads[idx];
    float xn = ads / g_cmax[b * NM + m];
    float num = powf(fmaxf(xn, 0.f), ha);
    float hill = num / (num + powf(hg, ha) + 1e-8f);
    g_hill[idx] = hill;
    g_u[idx] = hill + g_Z[idx];
}

// ---------------- reg_term + bias constant ----------------
__global__ void const_k(const float* __restrict__ reg_emb, const float* __restrict__ bias) {
    __shared__ float sm[256];
    float a = 0.f;
    for (int k = threadIdx.x; k < NH; k += 256) a += reg_emb[k];  // row 0 of (2,H)
    sm[threadIdx.x] = a;
    __syncthreads();
    for (int s = 128; s > 0; s >>= 1) {
        if (threadIdx.x < s) sm[threadIdx.x] += sm[threadIdx.x + s];
        __syncthreads();
    }
    if (threadIdx.x == 0) g_constant[0] = sm[0] * 0.3f + bias[0];
}

// ---------------- h init broadcast ----------------
__global__ void hinit_k(const float* __restrict__ h0) {
    int idx = blockIdx.x * 256 + threadIdx.x;      // NB*NH
    g_h[0][idx] = h0[idx % NH];
}

// ---------------- GRU step + (pipelined) output head ----------------
// grid 144: blocks 0..127 compute gates for step t (if t<NT),
//           blocks 128..143 compute the head for time t-1 (if t>=1).
__global__ void gru_step_k(int t,
                           const float* __restrict__ Wih, const float* __restrict__ Whh,
                           const float* __restrict__ bih, const float* __restrict__ bhh,
                           const float* __restrict__ Xc,
                           const float* __restrict__ wraw_w, const float* __restrict__ wraw_b,
                           float* __restrict__ y_out, float* __restrict__ wpos_out,
                           float* __restrict__ contrib_out) {
    __shared__ float s_w[144][33];   // 3 gates x 48 j rows, 32-wide k chunk (padded)
    __shared__ float s_x[32][33];    // [feature][local b]
    __shared__ float s_h[32][33];    // [k in chunk][local b]

    const float* h_in = g_h[t & 1];
    float* h_out = g_h[(t + 1) & 1];
    int blk = blockIdx.x;
    int tid = threadIdx.x;

    if (blk < 128) {
        if (t >= NT) return;
        int b0 = (blk & 7) * 32;       // 8 batch tiles of 32
        int j0 = (blk >> 3) * 48;      // 16 hidden tiles of 48
        int bl0 = (tid & 15) * 2;      // 2 local batches per thread
        int jl0 = (tid >> 4) * 3;      // 3 local hidden per thread

        // accumulators (biases folded in)
        float ar[2][3], az[2][3], ain[2][3], ahn[2][3];
        #pragma unroll
        for (int jj = 0; jj < 3; jj++) {
            int j = j0 + jl0 + jj;
            float br  = bih[j] + bhh[j];
            float bz  = bih[NH + j] + bhh[NH + j];
            float bni = bih[2*NH + j];
            float bnh = bhh[2*NH + j];
            #pragma unroll
            for (int bb = 0; bb < 2; bb++) {
                ar[bb][jj] = br; az[bb][jj] = bz; ain[bb][jj] = bni; ahn[bb][jj] = bnh;
            }
        }

        // ---- ih part: stage W_ih tile + x tile ----
        for (int idx = tid; idx < 144*32; idx += 256) {
            int rr = idx >> 5, k = idx & 31;
            int g = rr / 48, jl = rr - g * 48;
            s_w[rr][k] = Wih[((size_t)(g*NH + j0 + jl)) * 32 + k];
        }
        for (int idx = tid; idx < 32*32; idx += 256) {
            int bl = idx >> 5, f = idx & 31;
            size_t base = ((size_t)(b0 + bl) * NT + t) * NM;
            float v = (f < NM) ? g_u[base + f] : Xc[base + (f - NM)];
            s_x[f][bl] = v;
        }
        __syncthreads();
        #pragma unroll 4
        for (int f = 0; f < 32; f++) {
            float x0 = s_x[f][bl0], x1 = s_x[f][bl0 + 1];
            #pragma unroll
            for (int jj = 0; jj < 3; jj++) {
                float wr = s_w[jl0 + jj][f];
                float wz = s_w[48 + jl0 + jj][f];
                float wn = s_w[96 + jl0 + jj][f];
                ar[0][jj]  = fmaf(x0, wr, ar[0][jj]);  ar[1][jj]  = fmaf(x1, wr, ar[1][jj]);
                az[0][jj]  = fmaf(x0, wz, az[0][jj]);  az[1][jj]  = fmaf(x1, wz, az[1][jj]);
                ain[0][jj] = fmaf(x0, wn, ain[0][jj]); ain[1][jj] = fmaf(x1, wn, ain[1][jj]);
            }
        }
        __syncthreads();

        // ---- hh part: 24 chunks of 32 along k ----
        for (int kc = 0; kc < NH; kc += 32) {
            for (int idx = tid; idx < 144*32; idx += 256) {
                int rr = idx >> 5, k = idx & 31;
                int g = rr / 48, jl = rr - g * 48;
                s_w[rr][k] = Whh[((size_t)(g*NH + j0 + jl)) * NH + kc + k];
            }
            for (int idx = tid; idx < 32*32; idx += 256) {
                int bl = idx >> 5, k = idx & 31;
                s_h[k][bl] = h_in[(size_t)(b0 + bl) * NH + kc + k];
            }
            __syncthreads();
            #pragma unroll 8
            for (int k = 0; k < 32; k++) {
                float h0v = s_h[k][bl0], h1v = s_h[k][bl0 + 1];
                #pragma unroll
                for (int jj = 0; jj < 3; jj++) {
                    float wr = s_w[jl0 + jj][k];
                    float wz = s_w[48 + jl0 + jj][k];
                    float wn = s_w[96 + jl0 + jj][k];
                    ar[0][jj]  = fmaf(h0v, wr, ar[0][jj]);  ar[1][jj]  = fmaf(h1v, wr, ar[1][jj]);
                    az[0][jj]  = fmaf(h0v, wz, az[0][jj]);  az[1][jj]  = fmaf(h1v, wz, az[1][jj]);
                    ahn[0][jj] = fmaf(h0v, wn, ahn[0][jj]); ahn[1][jj] = fmaf(h1v, wn, ahn[1][jj]);
                }
            }
            __syncthreads();
        }

        // ---- finalize gates ----
        #pragma unroll
        for (int bb = 0; bb < 2; bb++) {
            int b = b0 + bl0 + bb;
            #pragma unroll
            for (int jj = 0; jj < 3; jj++) {
                int j = j0 + jl0 + jj;
                float rv = 1.f / (1.f + __expf(-ar[bb][jj]));
                float zv = 1.f / (1.f + __expf(-az[bb][jj]));
                float nv = tanhf(fmaf(rv, ahn[bb][jj], ain[bb][jj]));
                float hp = h_in[(size_t)b * NH + j];
                h_out[(size_t)b * NH + j] = fmaf(zv, hp - nv, nv);  // (1-z)n + z h
            }
        }
    } else {
        // ---- head for time tt = t-1 using h_in (state after step t-1) ----
        if (t < 1) return;
        int tt = t - 1;
        int hid = blk - 128;
        int m = tid & 15;
        int b = hid * 16 + (tid >> 4);
        const float* hrow = h_in + (size_t)b * NH;
        const float* wrow = wraw_w + (size_t)m * NH;
        float a = 0.f;
        #pragma unroll 8
        for (int k = 0; k < NH; k++) a = fmaf(__ldg(hrow + k), __ldg(wrow + k), a);
        float x = a + wraw_b[m];
        float wpos = fmaxf(x, 0.f) + log1pf(__expf(-fabsf(x)));  // softplus
        size_t oidx = ((size_t)b * NT + tt) * NM + m;
        wpos_out[oidx] = wpos;
        float c = g_hill[oidx] * wpos;
        contrib_out[oidx] = c;
        float s = c;
        #pragma unroll
        for (int off = 8; off > 0; off >>= 1) s += __shfl_xor_sync(0xffffffffu, s, off);
        if (m == 0) y_out[(size_t)b * NT + tt] = s + g_ctrl[(size_t)b * NT + tt] + g_constant[0];
    }
}

// ---------------- t=0 blend fixup ----------------
__global__ void fixup_k(float* __restrict__ y_out, float* __restrict__ wpos_out,
                        float* __restrict__ contrib_out) {
    int tid = blockIdx.x * 256 + threadIdx.x;  // 4096
    int b = tid >> 4, m = tid & 15;
    size_t i0 = ((size_t)b * NT + 0) * NM + m;
    size_t i1 = ((size_t)b * NT + 1) * NM + m;
    float w0 = 0.5f * wpos_out[i1] + 0.5f * wpos_out[i0];
    wpos_out[i0] = w0;
    float c = g_hill[i0] * w0;
    contrib_out[i0] = c;
    float s = c;
    #pragma unroll
    for (int off = 8; off > 0; off >>= 1) s += __shfl_xor_sync(0xffffffffu, s, off);
    if (m == 0) y_out[(size_t)b * NT] = s + g_ctrl[(size_t)b * NT] + g_constant[0];
}

// ---------------- launcher ----------------
extern "C" void kernel_launch(void* const* d_in, const int* in_sizes, int n_in,
                              void* d_out, int out_size) {
    const float* Xm   = (const float*)d_in[0];
    const float* Xc   = (const float*)d_in[1];
    /* d_in[2] = R (int32) unused in forward output */
    const float* A    = (const float*)d_in[3];
    const float* ew1  = (const float*)d_in[4];
    const float* eb1  = (const float*)d_in[5];
    const float* ew2  = (const float*)d_in[6];
    const float* eb2  = (const float*)d_in[7];
    const float* nw   = (const float*)d_in[8];
    const float* nb   = (const float*)d_in[9];
    const float* Wih  = (const float*)d_in[10];
    const float* Whh  = (const float*)d_in[11];
    const float* bih  = (const float*)d_in[12];
    const float* bhh  = (const float*)d_in[13];
    const float* ww   = (const float*)d_in[14];
    const float* wb   = (const float*)d_in[15];
    const float* alpha= (const float*)d_in[16];
    const float* ha   = (const float*)d_in[17];
    const float* hg   = (const float*)d_in[18];
    const float* cw   = (const float*)d_in[19];
    const float* cb   = (const float*)d_in[20];
    const float* re   = (const float*)d_in[21];
    const float* bias = (const float*)d_in[22];
    const float* h0   = (const float*)d_in[23];

    float* y  = (float*)d_out;                 // [B,T]
    float* wp = y + (size_t)NB * NT;           // [B,T,M]
    float* ct = wp + (size_t)NB * NT * NM;     // [B,T,M]

    encoder_k<<<NB*NT/256, 256>>>(Xm, ew1, eb1, ew2, eb2, nw, nb, A);
    ctrl_k<<<NB*NT/256, 256>>>(Xc, cw, cb);
    adstock_k<<<NB*NM/256, 256>>>(Xm, alpha);
    hill_k<<<NB*NT*NM/256, 256>>>(ha, hg);
    const_k<<<1, 256>>>(re, bias);
    hinit_k<<<NB*NH/256, 256>>>(h0);

    for (int t = 0; t <= NT; t++) {
        gru_step_k<<<144, 256>>>(t, Wih, Whh, bih, bhh, Xc, ww, wb, y, wp, ct);
    }
    fixup_k<<<NB*NM/256, 256>>>(y, wp, ct);
}